// round 6
// baseline (speedup 1.0000x reference)
#include <cuda_runtime.h>
#include <cstdint>

#define TOPK     20
#define ROW      32000
#define NROWS    4096
#define TOT_F4   32768000       // 4096 * 8000 float4 elements
#define TOT_SC   131072000      // total scalars
#define DIM      1024
#define NB       4
#define NPROTO   64
#define NCHUNK   128            // pool chunks (8 tokens each)
#define CAPC     192            // per-row candidate capacity
#define THR0     2.75f          // top-20-of-32000 N(0,1) threshold (quantile ~3.23)
#define C1B      6              // float4 loads in flight per thread
#define NCTA     888            // persistent copy CTAs = 148 SMs * 6
#define MAXROWS  8              // max rows a copy CTA can span

// -------- device scratch (static __device__, no allocations) --------
__device__ float              g_part[NB * NCHUNK * DIM];   // 2 MB
__device__ int                g_flag[NB];
__device__ int                g_ccnt[NROWS];
__device__ int                g_done[NROWS];
__device__ unsigned long long g_cand[NROWS * CAPC];        // ~6 MB

// =======================================================================
// helpers
// =======================================================================
__device__ __forceinline__ unsigned long long umax64(unsigned long long a,
                                                     unsigned long long b) {
    return a > b ? a : b;
}
__device__ __forceinline__ unsigned long long make_key(float v, int col) {
    unsigned u   = __float_as_uint(v);
    unsigned sbl = (u & 0x80000000u) ? ~u : (u | 0x80000000u);
    return ((unsigned long long)sbl << 32) |
           (unsigned long long)(0xFFFFFFFFu - (unsigned)col);
}

// =======================================================================
// K1: token-chunk partial sums of hidden (512 blocks x 256 thr, MLP=8)
//     block = (batch, chunk of 8 tokens); thread = float4 column
//     also zeroes per-row candidate + completion counters
// =======================================================================
__global__ __launch_bounds__(256, 4)
void pool_kernel(const float* __restrict__ hidden) {
    int blk = blockIdx.x;
    int b   = blk >> 7;                 // /128
    int c   = blk & 127;
    int d4  = threadIdx.x;              // 0..255 float4 columns

    const float4* p = (const float4*)(hidden
                    + (size_t)b * (1024 * DIM) + (size_t)c * 8 * DIM) + d4;
    float4 r[8];
    #pragma unroll
    for (int t = 0; t < 8; ++t) r[t] = p[t * 256];
    float4 s = r[0];
    #pragma unroll
    for (int t = 1; t < 8; ++t) {
        s.x += r[t].x; s.y += r[t].y; s.z += r[t].z; s.w += r[t].w;
    }
    ((float4*)g_part)[(size_t)(b * NCHUNK + c) * 256 + d4] = s;

    if (blk < 16) {
        int i = blk * 256 + threadIdx.x;
        g_ccnt[i] = 0;
        g_done[i] = 0;
    }
}

// =======================================================================
// K2: flag[b] = sign( sum_p (emb . proto_p)/max(||proto_p||,eps) ) > 0
//     (positive common factors 1/64 and 1/||emb|| dropped)
// =======================================================================
__global__ void flag_kernel(const float* __restrict__ proto) {
    __shared__ float s_emb[DIM];
    __shared__ float s_sim[32];
    int b    = blockIdx.x;
    int tid  = threadIdx.x;
    int w    = tid >> 5;
    int lane = tid & 31;

    float e = 0.f;
    #pragma unroll 8
    for (int c = 0; c < NCHUNK; ++c) e += g_part[(b * NCHUNK + c) * DIM + tid];
    s_emb[tid] = e;
    __syncthreads();

    float acc = 0.f;
    for (int p = w; p < NPROTO; p += 32) {
        float sq = 0.f, dt = 0.f;
        for (int d = lane; d < DIM; d += 32) {
            float x = proto[p * DIM + d];
            sq += x * x;
            dt += x * s_emb[d];
        }
        #pragma unroll
        for (int o = 16; o; o >>= 1) {
            sq += __shfl_xor_sync(0xFFFFFFFFu, sq, o);
            dt += __shfl_xor_sync(0xFFFFFFFFu, dt, o);
        }
        acc += dt / fmaxf(sqrtf(sq), 1e-8f);
    }
    if (lane == 0) s_sim[w] = acc;
    __syncthreads();
    if (tid == 0) {
        float t = 0.f;
        #pragma unroll
        for (int i = 0; i < 32; ++i) t += s_sim[i];
        g_flag[b] = (t > 0.f) ? 1 : 0;
    }
}

// =======================================================================
// K3: persistent streaming copy + candidate gather + fused patch epilogue
//     888 CTAs, each owns one contiguous range (no wave quantization)
// =======================================================================
__global__ __launch_bounds__(256, 6)
void copy_kernel(const float* __restrict__ logits, float* __restrict__ out) {
    const float4* __restrict__ src4 = (const float4*)logits;
    float4*       __restrict__ dst4 = (float4*)out;
    int tid = threadIdx.x;

    int F0 = (int)((long long)blockIdx.x       * TOT_F4 / NCTA);
    int F1 = (int)((long long)(blockIdx.x + 1) * TOT_F4 / NCTA);

    // ---- streaming main body ----
    for (int base = F0; base < F1; base += 256 * C1B) {
        float4 r[C1B];
        #pragma unroll
        for (int k = 0; k < C1B; ++k) {
            int ix = base + k * 256 + tid;
            r[k] = (ix < F1) ? __ldcs(&src4[ix])
                             : make_float4(0.f, 0.f, 0.f, 0.f);
        }
        #pragma unroll
        for (int k = 0; k < C1B; ++k) {
            int ix = base + k * 256 + tid;
            if (ix < F1) __stcs(&dst4[ix], r[k]);
        }
        #pragma unroll
        for (int k = 0; k < C1B; ++k) {
            int ix = base + k * 256 + tid;
            if (ix < F1) {
                float mx = fmaxf(fmaxf(r[k].x, r[k].y), fmaxf(r[k].z, r[k].w));
                if (mx > THR0) {
                    float vv[4] = {r[k].x, r[k].y, r[k].z, r[k].w};
                    #pragma unroll
                    for (int c = 0; c < 4; ++c) {
                        if (vv[c] > THR0) {
                            int g   = ix * 4 + c;
                            int row = g / ROW;
                            int col = g - row * ROW;
                            int slot = atomicAdd(&g_ccnt[row], 1);
                            if (slot < CAPC)
                                g_cand[row * CAPC + slot] = make_key(vv[c], col);
                        }
                    }
                }
            }
        }
    }

    // ---- completion accounting (threadfence-reduction pattern) ----
    __shared__ int s_patch[MAXROWS];
    __shared__ int s_np;
    if (tid == 0) s_np = 0;
    __syncthreads();                   // all block stores/gathers done

    if (tid == 0) {
        int S0 = F0 * 4;
        int S1 = F1 * 4;
        int r0 = S0 / ROW;
        int r1 = (S1 - 1) / ROW;
        __threadfence();               // publish this block's writes
        int np = 0;
        for (int r = r0; r <= r1; ++r) {
            int a = max(S0, r * ROW);
            int e = min(S1, (r + 1) * ROW);
            int old = atomicAdd(&g_done[r], e - a);
            if (old + (e - a) == ROW && np < MAXROWS) s_patch[np++] = r;
        }
        s_np = np;
    }
    __syncthreads();
    int np = s_np;
    if (np == 0) return;

    // ---- all 8 warps patch completed rows (round-robin) ----
    __threadfence();                   // acquire: see other blocks' cand writes
    int w    = tid >> 5;
    int lane = tid & 31;
    for (int pi = w; pi < np; pi += 8) {
        int row = s_patch[pi];
        int b   = row >> 10;
        if (!g_flag[b]) continue;
        float* dst = out + (size_t)row * ROW;
        int cnt = g_ccnt[row];

        if (cnt >= TOPK && cnt <= CAPC) {
            // fast path: rank counting over <=192 unique keys
            const unsigned long long* cp = g_cand + (size_t)row * CAPC;
            unsigned long long mk[6];
            #pragma unroll
            for (int j = 0; j < 6; ++j) {
                int i = lane + j * 32;
                mk[j] = (i < cnt) ? cp[i] : 0ULL;
            }
            int rk[6] = {0, 0, 0, 0, 0, 0};
            #pragma unroll 4
            for (int i = 0; i < cnt; ++i) {
                unsigned long long ki = cp[i];
                #pragma unroll
                for (int j = 0; j < 6; ++j) rk[j] += (ki > mk[j]);
            }
            #pragma unroll
            for (int j = 0; j < 6; ++j) {
                int i = lane + j * 32;
                if (i < cnt && rk[j] < TOPK) {
                    unsigned col = 0xFFFFFFFFu - (unsigned)mk[j];
                    if (col < ROW) dst[col] = -100.0f;
                }
            }
        } else {
            // deterministic slow path (statistically never taken):
            // 20 passes, monotonically descending unique keys
            const float* srcr = logits + (size_t)row * ROW;
            unsigned long long prev = ~0ULL;
            for (int t = 0; t < TOPK; ++t) {
                unsigned long long best = 0ULL;
                for (int i = lane; i < ROW; i += 32) {
                    unsigned long long key = make_key(srcr[i], i);
                    if (key < prev) best = umax64(best, key);
                }
                #pragma unroll
                for (int o = 16; o; o >>= 1)
                    best = umax64(best, __shfl_xor_sync(0xFFFFFFFFu, best, o));
                prev = best;
                unsigned col = 0xFFFFFFFFu - (unsigned)best;
                if (lane == 0 && best != 0ULL && col < ROW)
                    dst[col] = -100.0f;
            }
        }
    }
}

// =======================================================================
extern "C" void kernel_launch(void* const* d_in, const int* in_sizes, int n_in,
                              void* d_out, int out_size) {
    const float* proto  = (const float*)d_in[0];  // [64, 1024]
    const float* hidden = (const float*)d_in[1];  // [4, 1024, 1024]
    const float* logits = (const float*)d_in[2];  // [4, 1, 1024, 32000]
    float* out = (float*)d_out;

    pool_kernel<<<NB * NCHUNK, 256>>>(hidden);
    flag_kernel<<<NB, 1024>>>(proto);
    copy_kernel<<<NCTA, 256>>>(logits, out);
}

// round 7
// speedup vs baseline: 1.2274x; 1.2274x over previous
#include <cuda_runtime.h>
#include <cstdint>

#define TOPK     20
#define ROW      32000
#define NROWS    4096
#define TOT_F4   32768000       // 4096 * 8000 float4 elements
#define TOT_SC   131072000      // total scalars
#define DIM      1024
#define NB       4
#define NPROTO   64
#define NCHUNK   128            // pool chunks (8 tokens each)
#define CAPC     192            // per-row candidate capacity
#define THR0     2.75f          // top-20-of-32000 N(0,1) threshold (quantile ~3.23)
#define C1B      6              // float4 loads in flight per thread
#define CTA_F4   (256 * C1B * 4)    // 6144 float4 per CTA (96KB)
#define CTA_SC   (CTA_F4 * 4)       // 24576 scalars per CTA (< ROW => <=2 rows)

// -------- device scratch (static __device__, no allocations) --------
__device__ float              g_part[NB * NCHUNK * DIM];   // 2 MB
__device__ int                g_flag[NB];
__device__ int                g_ccnt[NROWS];
__device__ int                g_done[NROWS];
__device__ unsigned long long g_cand[NROWS * CAPC];        // ~6 MB

// =======================================================================
// helpers
// =======================================================================
__device__ __forceinline__ unsigned long long umax64(unsigned long long a,
                                                     unsigned long long b) {
    return a > b ? a : b;
}
__device__ __forceinline__ unsigned long long make_key(float v, int col) {
    unsigned u   = __float_as_uint(v);
    unsigned sbl = (u & 0x80000000u) ? ~u : (u | 0x80000000u);
    return ((unsigned long long)sbl << 32) |
           (unsigned long long)(0xFFFFFFFFu - (unsigned)col);
}

// =======================================================================
// K1: token-chunk partial sums of hidden (512 blocks x 256 thr, MLP=8)
//     block = (batch, chunk of 8 tokens); thread = float4 column
//     also zeroes per-row candidate + completion counters
// =======================================================================
__global__ __launch_bounds__(256, 4)
void pool_kernel(const float* __restrict__ hidden) {
    int blk = blockIdx.x;
    int b   = blk >> 7;                 // /128
    int c   = blk & 127;
    int d4  = threadIdx.x;              // 0..255 float4 columns

    const float4* p = (const float4*)(hidden
                    + (size_t)b * (1024 * DIM) + (size_t)c * 8 * DIM) + d4;
    float4 r[8];
    #pragma unroll
    for (int t = 0; t < 8; ++t) r[t] = p[t * 256];
    float4 s = r[0];
    #pragma unroll
    for (int t = 1; t < 8; ++t) {
        s.x += r[t].x; s.y += r[t].y; s.z += r[t].z; s.w += r[t].w;
    }
    ((float4*)g_part)[(size_t)(b * NCHUNK + c) * 256 + d4] = s;

    if (blk < 16) {
        int i = blk * 256 + threadIdx.x;
        g_ccnt[i] = 0;
        g_done[i] = 0;
    }
}

// =======================================================================
// K2: flag[b] = sign( sum_p (emb . proto_p)/max(||proto_p||,eps) ) > 0
//     (positive common factors 1/64 and 1/||emb|| dropped)
// =======================================================================
__global__ void flag_kernel(const float* __restrict__ proto) {
    __shared__ float s_emb[DIM];
    __shared__ float s_sim[32];
    int b    = blockIdx.x;
    int tid  = threadIdx.x;
    int w    = tid >> 5;
    int lane = tid & 31;

    float e = 0.f;
    #pragma unroll 8
    for (int c = 0; c < NCHUNK; ++c) e += g_part[(b * NCHUNK + c) * DIM + tid];
    s_emb[tid] = e;
    __syncthreads();

    float acc = 0.f;
    for (int p = w; p < NPROTO; p += 32) {
        float sq = 0.f, dt = 0.f;
        for (int d = lane; d < DIM; d += 32) {
            float x = proto[p * DIM + d];
            sq += x * x;
            dt += x * s_emb[d];
        }
        #pragma unroll
        for (int o = 16; o; o >>= 1) {
            sq += __shfl_xor_sync(0xFFFFFFFFu, sq, o);
            dt += __shfl_xor_sync(0xFFFFFFFFu, dt, o);
        }
        acc += dt / fmaxf(sqrtf(sq), 1e-8f);
    }
    if (lane == 0) s_sim[w] = acc;
    __syncthreads();
    if (tid == 0) {
        float t = 0.f;
        #pragma unroll
        for (int i = 0; i < 32; ++i) t += s_sim[i];
        g_flag[b] = (t > 0.f) ? 1 : 0;
    }
}

// =======================================================================
// K3: blocked streaming copy + candidate gather + fused patch epilogue
//     grid 5334, each CTA a contiguous 96KB block (TLB-friendly waves)
// =======================================================================
__device__ __forceinline__ void gather_f4(float4 v, int ix) {
    float mx = fmaxf(fmaxf(v.x, v.y), fmaxf(v.z, v.w));
    if (mx > THR0) {
        float vv[4] = {v.x, v.y, v.z, v.w};
        #pragma unroll
        for (int c = 0; c < 4; ++c) {
            if (vv[c] > THR0) {
                int g   = ix * 4 + c;
                int row = g / ROW;
                int col = g - row * ROW;
                int slot = atomicAdd(&g_ccnt[row], 1);
                if (slot < CAPC)
                    g_cand[row * CAPC + slot] = make_key(vv[c], col);
            }
        }
    }
}

__global__ __launch_bounds__(256, 6)
void copy_kernel(const float* __restrict__ logits, float* __restrict__ out) {
    const float4* __restrict__ src4 = (const float4*)logits;
    float4*       __restrict__ dst4 = (float4*)out;
    int tid  = threadIdx.x;
    int base = blockIdx.x * CTA_F4;
    bool full = (base + CTA_F4 <= TOT_F4);   // all but the last CTA

    // ---- streaming main body ----
    if (full) {
        #pragma unroll
        for (int it = 0; it < 4; ++it) {
            int b0 = base + it * (256 * C1B) + tid;
            float4 r[C1B];
            #pragma unroll
            for (int k = 0; k < C1B; ++k) r[k] = __ldcs(&src4[b0 + k * 256]);
            #pragma unroll
            for (int k = 0; k < C1B; ++k) __stcs(&dst4[b0 + k * 256], r[k]);
            #pragma unroll
            for (int k = 0; k < C1B; ++k) gather_f4(r[k], b0 + k * 256);
        }
    } else {
        #pragma unroll
        for (int it = 0; it < 4; ++it) {
            int b0 = base + it * (256 * C1B) + tid;
            float4 r[C1B];
            #pragma unroll
            for (int k = 0; k < C1B; ++k) {
                int ix = b0 + k * 256;
                r[k] = (ix < TOT_F4) ? __ldcs(&src4[ix])
                                     : make_float4(0.f, 0.f, 0.f, 0.f);
            }
            #pragma unroll
            for (int k = 0; k < C1B; ++k) {
                int ix = b0 + k * 256;
                if (ix < TOT_F4) __stcs(&dst4[ix], r[k]);
            }
            #pragma unroll
            for (int k = 0; k < C1B; ++k) {
                int ix = b0 + k * 256;
                if (ix < TOT_F4) gather_f4(r[k], ix);
            }
        }
    }

    // ---- completion accounting (threadfence-reduction pattern) ----
    __shared__ int s_patch[2];
    __shared__ int s_np;
    if (tid == 0) s_np = 0;
    __syncthreads();                   // all block stores/gathers done

    if (tid == 0) {
        int S0 = base * 4;
        int S1 = min(S0 + CTA_SC, TOT_SC);
        int r0 = S0 / ROW;
        int r1 = (S1 - 1) / ROW;       // r1 - r0 <= 1 since CTA_SC < ROW
        __threadfence();               // publish this block's writes
        int np = 0;
        for (int r = r0; r <= r1; ++r) {
            int a = max(S0, r * ROW);
            int e = min(S1, (r + 1) * ROW);
            int old = atomicAdd(&g_done[r], e - a);
            if (old + (e - a) == ROW) s_patch[np++] = r;
        }
        s_np = np;
    }
    __syncthreads();
    int np = s_np;
    if (np == 0 || tid >= 32) return;

    // ---- warp 0 patches each completed row ----
    __threadfence();                   // acquire: see other blocks' cand writes
    int lane = tid;
    for (int pi = 0; pi < np; ++pi) {
        int row = s_patch[pi];
        int b   = row >> 10;
        if (!g_flag[b]) continue;
        float* dst = out + (size_t)row * ROW;
        int cnt = g_ccnt[row];

        if (cnt >= TOPK && cnt <= CAPC) {
            // fast path: rank counting over <=192 unique keys
            const unsigned long long* cp = g_cand + (size_t)row * CAPC;
            unsigned long long mk[6];
            #pragma unroll
            for (int j = 0; j < 6; ++j) {
                int i = lane + j * 32;
                mk[j] = (i < cnt) ? cp[i] : 0ULL;
            }
            int rk[6] = {0, 0, 0, 0, 0, 0};
            #pragma unroll 4
            for (int i = 0; i < cnt; ++i) {
                unsigned long long ki = cp[i];
                #pragma unroll
                for (int j = 0; j < 6; ++j) rk[j] += (ki > mk[j]);
            }
            #pragma unroll
            for (int j = 0; j < 6; ++j) {
                int i = lane + j * 32;
                if (i < cnt && rk[j] < TOPK) {
                    unsigned col = 0xFFFFFFFFu - (unsigned)mk[j];
                    if (col < ROW) dst[col] = -100.0f;
                }
            }
        } else {
            // deterministic slow path (statistically never taken):
            // 20 passes, monotonically descending unique keys
            const float* srcr = logits + (size_t)row * ROW;
            unsigned long long prev = ~0ULL;
            for (int t = 0; t < TOPK; ++t) {
                unsigned long long best = 0ULL;
                for (int i = lane; i < ROW; i += 32) {
                    unsigned long long key = make_key(srcr[i], i);
                    if (key < prev) best = umax64(best, key);
                }
                #pragma unroll
                for (int o = 16; o; o >>= 1)
                    best = umax64(best, __shfl_xor_sync(0xFFFFFFFFu, best, o));
                prev = best;
                unsigned col = 0xFFFFFFFFu - (unsigned)best;
                if (lane == 0 && best != 0ULL && col < ROW)
                    dst[col] = -100.0f;
            }
        }
    }
}

// =======================================================================
extern "C" void kernel_launch(void* const* d_in, const int* in_sizes, int n_in,
                              void* d_out, int out_size) {
    const float* proto  = (const float*)d_in[0];  // [64, 1024]
    const float* hidden = (const float*)d_in[1];  // [4, 1024, 1024]
    const float* logits = (const float*)d_in[2];  // [4, 1, 1024, 32000]
    float* out = (float*)d_out;

    pool_kernel<<<NB * NCHUNK, 256>>>(hidden);
    flag_kernel<<<NB, 1024>>>(proto);
    int grid_copy = (TOT_F4 + CTA_F4 - 1) / CTA_F4;   // 5334
    copy_kernel<<<grid_copy, 256>>>(logits, out);
}